// round 3
// baseline (speedup 1.0000x reference)
#include <cuda_runtime.h>
#include <math.h>

constexpr int H = 1024;
constexpr int V = 50257;
constexpr int L = 4096;
constexpr int NPART = 32;   // LSE partial blocks

// Persistent scratch (no allocation allowed).
__device__ float g_hnew[H];
__device__ float g_concat[2 * H];   // [0:H) = ctx (atomicAdd target), [H:2H) = h_new
__device__ float g_scores[L];
__device__ float g_attn[L];
__device__ float g_logits[V];
__device__ float g_pmax[NPART];
__device__ float g_psum[NPART];

__device__ __forceinline__ float dot4(float4 a, float4 b) {
    return a.x * b.x + a.y * b.y + a.z * b.z + a.w * b.w;
}
__device__ __forceinline__ float warp_sum(float v) {
#pragma unroll
    for (int o = 16; o; o >>= 1) v += __shfl_xor_sync(0xffffffffu, v, o);
    return v;
}
__device__ __forceinline__ float warp_max(float v) {
#pragma unroll
    for (int o = 16; o; o >>= 1) v = fmaxf(v, __shfl_xor_sync(0xffffffffu, v, o));
    return v;
}

// ---------------------------------------------------------------------------
// 1) GRU step: 1024 blocks (one per output element j), 256 threads.
//    Weights read with __ldcs (single-use, keep them out of L2).
// ---------------------------------------------------------------------------
__global__ void gru_kernel(const int* __restrict__ input,
                           const float* __restrict__ hidden,
                           const float* __restrict__ embedding,
                           const float* __restrict__ w_ih,
                           const float* __restrict__ w_hh,
                           const float* __restrict__ b_ih,
                           const float* __restrict__ b_hh,
                           float* __restrict__ d_out) {
    const int j = blockIdx.x;
    const int t = threadIdx.x;
    const int tok = input[0];  // low word: ok for int32 or LE int64, 0<=tok<V

    const float4* x4 = (const float4*)(embedding + (size_t)tok * H);
    const float4* h4 = (const float4*)hidden;
    const float4 xv = x4[t];
    const float4 hv = h4[t];

    const float4* wir = (const float4*)(w_ih + (size_t)j * H);
    const float4* wiz = (const float4*)(w_ih + (size_t)(H + j) * H);
    const float4* win = (const float4*)(w_ih + (size_t)(2 * H + j) * H);
    const float4* whr = (const float4*)(w_hh + (size_t)j * H);
    const float4* whz = (const float4*)(w_hh + (size_t)(H + j) * H);
    const float4* whn = (const float4*)(w_hh + (size_t)(2 * H + j) * H);

    float s0 = dot4(__ldcs(&wir[t]), xv);
    float s1 = dot4(__ldcs(&wiz[t]), xv);
    float s2 = dot4(__ldcs(&win[t]), xv);
    float s3 = dot4(__ldcs(&whr[t]), hv);
    float s4 = dot4(__ldcs(&whz[t]), hv);
    float s5 = dot4(__ldcs(&whn[t]), hv);

    __shared__ float red[8][6];
    s0 = warp_sum(s0); s1 = warp_sum(s1); s2 = warp_sum(s2);
    s3 = warp_sum(s3); s4 = warp_sum(s4); s5 = warp_sum(s5);
    const int w = t >> 5, lane = t & 31;
    if (lane == 0) {
        red[w][0] = s0; red[w][1] = s1; red[w][2] = s2;
        red[w][3] = s3; red[w][4] = s4; red[w][5] = s5;
    }
    __syncthreads();
    if (t == 0) {
        float a[6] = {0, 0, 0, 0, 0, 0};
#pragma unroll
        for (int i = 0; i < 8; i++)
#pragma unroll
            for (int k = 0; k < 6; k++) a[k] += red[i][k];
        const float r = 1.f / (1.f + __expf(-(a[0] + b_ih[j] + a[3] + b_hh[j])));
        const float z = 1.f / (1.f + __expf(-(a[1] + b_ih[H + j] + a[4] + b_hh[H + j])));
        const float n = tanhf(a[2] + b_ih[2 * H + j] + r * (a[5] + b_hh[2 * H + j]));
        const float hn = (1.f - z) * n + z * hidden[j];
        g_hnew[j] = hn;
        g_concat[H + j] = hn;
        d_out[V + j] = hn;  // second tuple element of the reference output
    }
}

// ---------------------------------------------------------------------------
// 2) Attention scores: warp per encoder row. enc stays L2-resident (default
//    caching) since the big streams use __ldcs.
// ---------------------------------------------------------------------------
__global__ void scores_kernel(const float* __restrict__ enc) {
    const int w = threadIdx.x >> 5, lane = threadIdx.x & 31;
    const int l = blockIdx.x * 8 + w;
    const float4* e4 = (const float4*)(enc + (size_t)l * H);
    const float4* h4 = (const float4*)g_hnew;
    float s = 0.f;
#pragma unroll
    for (int i = 0; i < 8; i++) s += dot4(e4[lane + i * 32], h4[lane + i * 32]);
    s = warp_sum(s);
    if (lane == 0) g_scores[l] = s;
}

// ---------------------------------------------------------------------------
// 3) Softmax over L=4096 scores; one 1024-thread block. Also re-zeroes the
//    ctx accumulator for this replay.
// ---------------------------------------------------------------------------
__global__ void softmax_kernel() {
    const int t = threadIdx.x;
    __shared__ float red[32];
    __shared__ float bmax, bsum;

    const float v0 = g_scores[t];
    const float v1 = g_scores[t + 1024];
    const float v2 = g_scores[t + 2048];
    const float v3 = g_scores[t + 3072];

    float m = fmaxf(fmaxf(v0, v1), fmaxf(v2, v3));
    m = warp_max(m);
    if ((t & 31) == 0) red[t >> 5] = m;
    __syncthreads();
    if (t < 32) {
        float x = red[t];
        x = warp_max(x);
        if (t == 0) bmax = x;
    }
    __syncthreads();
    const float mm = bmax;

    const float e0 = __expf(v0 - mm), e1 = __expf(v1 - mm);
    const float e2 = __expf(v2 - mm), e3 = __expf(v3 - mm);
    float s = e0 + e1 + e2 + e3;
    s = warp_sum(s);
    if ((t & 31) == 0) red[t >> 5] = s;
    __syncthreads();
    if (t < 32) {
        float x = red[t];
        x = warp_sum(x);
        if (t == 0) bsum = x;
    }
    __syncthreads();
    const float inv = 1.f / bsum;

    g_attn[t]        = e0 * inv;
    g_attn[t + 1024] = e1 * inv;
    g_attn[t + 2048] = e2 * inv;
    g_attn[t + 3072] = e3 * inv;
    g_concat[t] = 0.f;  // re-zero ctx accumulator each replay
}

// ---------------------------------------------------------------------------
// 4) ctx = attn @ E. 512 blocks × 8 rows; thread c owns float4 column c.
// ---------------------------------------------------------------------------
__global__ void ctx_kernel(const float* __restrict__ enc) {
    const int c = threadIdx.x;        // float4 column 0..255
    const int l0 = blockIdx.x * 8;
    __shared__ float a[8];
    if (c < 8) a[c] = g_attn[l0 + c];
    __syncthreads();

    const float4* e4 = (const float4*)enc;
    float4 acc = make_float4(0.f, 0.f, 0.f, 0.f);
#pragma unroll
    for (int i = 0; i < 8; i++) {
        const float4 e = e4[(size_t)(l0 + i) * 256 + c];
        const float w = a[i];
        acc.x += w * e.x; acc.y += w * e.y;
        acc.z += w * e.z; acc.w += w * e.w;
    }
    float* dst = g_concat + c * 4;
    atomicAdd(dst + 0, acc.x);
    atomicAdd(dst + 1, acc.y);
    atomicAdd(dst + 2, acc.z);
    atomicAdd(dst + 3, acc.w);
}

// ---------------------------------------------------------------------------
// 5) logits = out_w @ concat + out_b. 2 rows per warp, 16 rows per block;
//    __ldcs streaming weights; concat staged in shared.
// ---------------------------------------------------------------------------
__global__ void logits_kernel(const float* __restrict__ out_w,
                              const float* __restrict__ out_b) {
    __shared__ float4 csh[512];   // 2H floats
    const int t = threadIdx.x;
    const float4* cg = (const float4*)g_concat;
    csh[t] = cg[t];
    csh[t + 256] = cg[t + 256];
    __syncthreads();

    const int w = t >> 5, lane = t & 31;
    const int v0 = blockIdx.x * 16 + w * 2;
    if (v0 >= V) return;
    const bool hasB = (v0 + 1 < V);
    const float4* wa = (const float4*)(out_w + (size_t)v0 * 2 * H);
    const float4* wb = wa + 512;

    float sa = 0.f, sb = 0.f;
#pragma unroll
    for (int i = 0; i < 16; i++) {
        const float4 c = csh[lane + i * 32];
        const float4 A = __ldcs(&wa[lane + i * 32]);
        sa += dot4(A, c);
        if (hasB) {
            const float4 B = __ldcs(&wb[lane + i * 32]);
            sb += dot4(B, c);
        }
    }
    sa = warp_sum(sa);
    sb = warp_sum(sb);
    if (lane == 0) {
        g_logits[v0] = sa + out_b[v0];
        if (hasB) g_logits[v0 + 1] = sb + out_b[v0 + 1];
    }
}

// ---------------------------------------------------------------------------
// 6) LSE stage 1: 32 blocks × 256 threads -> (max, sumexp) per block.
// ---------------------------------------------------------------------------
__global__ void lse_part_kernel() {
    const int b = blockIdx.x, t = threadIdx.x;
    const int chunk = (V + NPART - 1) / NPART;        // 1571
    const int lo = b * chunk;
    const int hi = min(lo + chunk, V);

    __shared__ float red[8];
    __shared__ float bmax;

    float m = -3.4e38f;
    for (int i = lo + t; i < hi; i += 256) m = fmaxf(m, g_logits[i]);
    m = warp_max(m);
    if ((t & 31) == 0) red[t >> 5] = m;
    __syncthreads();
    if (t < 8) {
        float x = red[t];
#pragma unroll
        for (int o = 4; o; o >>= 1) x = fmaxf(x, __shfl_xor_sync(0xffu, x, o));
        if (t == 0) bmax = x;
    }
    __syncthreads();
    const float mm = bmax;

    float s = 0.f;
    for (int i = lo + t; i < hi; i += 256) s += __expf(g_logits[i] - mm);
    s = warp_sum(s);
    if ((t & 31) == 0) red[t >> 5] = s;
    __syncthreads();
    if (t < 8) {
        float x = red[t];
#pragma unroll
        for (int o = 4; o; o >>= 1) x += __shfl_xor_sync(0xffu, x, o);
        if (t == 0) { g_pmax[b] = mm; g_psum[b] = x; }
    }
}

// ---------------------------------------------------------------------------
// 7) finalize: warp 0 merges the 32 (max,sumexp) partials online, then the
//    whole block writes out[v] = logits[v] - lse.
// ---------------------------------------------------------------------------
__global__ void final_kernel(float* __restrict__ d_out) {
    __shared__ float lse_s;
    const int t = threadIdx.x;
    if (t < 32) {
        float m = g_pmax[t];
        float s = g_psum[t];
#pragma unroll
        for (int o = 16; o; o >>= 1) {
            const float om = __shfl_xor_sync(0xffffffffu, m, o);
            const float os = __shfl_xor_sync(0xffffffffu, s, o);
            const float M = fmaxf(m, om);
            s = s * __expf(m - M) + os * __expf(om - M);
            m = M;
        }
        if (t == 0) lse_s = m + logf(s);
    }
    __syncthreads();
    const float lse = lse_s;
    const int v = blockIdx.x * 256 + t;
    if (v < V) d_out[v] = g_logits[v] - lse;
}

extern "C" void kernel_launch(void* const* d_in, const int* in_sizes, int n_in,
                              void* d_out, int out_size) {
    const int*   input  = (const int*)d_in[0];
    const float* hidden = (const float*)d_in[1];
    const float* enc    = (const float*)d_in[2];
    const float* emb    = (const float*)d_in[3];
    const float* w_ih   = (const float*)d_in[4];
    const float* w_hh   = (const float*)d_in[5];
    const float* b_ih   = (const float*)d_in[6];
    const float* b_hh   = (const float*)d_in[7];
    const float* out_w  = (const float*)d_in[8];
    const float* out_b  = (const float*)d_in[9];
    float* out = (float*)d_out;

    gru_kernel<<<H, 256>>>(input, hidden, emb, w_ih, w_hh, b_ih, b_hh, out);
    scores_kernel<<<L / 8, 256>>>(enc);
    softmax_kernel<<<1, 1024>>>();
    ctx_kernel<<<L / 8, 256>>>(enc);
    logits_kernel<<<(V + 15) / 16, 256>>>(out_w, out_b);
    lse_part_kernel<<<NPART, 256>>>();
    final_kernel<<<(V + 255) / 256, 256>>>(out);
}

// round 4
// speedup vs baseline: 1.1109x; 1.1109x over previous
#include <cuda_runtime.h>
#include <math.h>

constexpr int H = 1024;
constexpr int V = 50257;
constexpr int L = 4096;
constexpr int NPART = 32;     // LSE partial blocks
constexpr int CPART = 128;    // ctx partial blocks (32 rows each)

// Persistent scratch (no allocation allowed).
__device__ float g_hnew[H];
__device__ float g_concat[2 * H];   // [0:H) = ctx, [H:2H) = h_new
__device__ float g_scores[L];
__device__ float g_attn[L];
__device__ float g_logits[V];
__device__ float g_pmax[NPART];
__device__ float g_psum[NPART];
__device__ float g_ctxp[CPART][H];  // 512 KB ctx partials

__device__ __forceinline__ float dot4(float4 a, float4 b) {
    return a.x * b.x + a.y * b.y + a.z * b.z + a.w * b.w;
}
__device__ __forceinline__ float warp_sum(float v) {
#pragma unroll
    for (int o = 16; o; o >>= 1) v += __shfl_xor_sync(0xffffffffu, v, o);
    return v;
}
__device__ __forceinline__ float warp_max(float v) {
#pragma unroll
    for (int o = 16; o; o >>= 1) v = fmaxf(v, __shfl_xor_sync(0xffffffffu, v, o));
    return v;
}

// ---------------------------------------------------------------------------
// 1) GRU step: 1024 blocks (one per output element j), 256 threads.
// ---------------------------------------------------------------------------
__global__ void gru_kernel(const int* __restrict__ input,
                           const float* __restrict__ hidden,
                           const float* __restrict__ embedding,
                           const float* __restrict__ w_ih,
                           const float* __restrict__ w_hh,
                           const float* __restrict__ b_ih,
                           const float* __restrict__ b_hh,
                           float* __restrict__ d_out) {
    const int j = blockIdx.x;
    const int t = threadIdx.x;
    const int tok = input[0];  // low word: ok for int32 or LE int64, 0<=tok<V

    const float4* x4 = (const float4*)(embedding + (size_t)tok * H);
    const float4* h4 = (const float4*)hidden;
    const float4 xv = x4[t];
    const float4 hv = h4[t];

    const float4* wir = (const float4*)(w_ih + (size_t)j * H);
    const float4* wiz = (const float4*)(w_ih + (size_t)(H + j) * H);
    const float4* win = (const float4*)(w_ih + (size_t)(2 * H + j) * H);
    const float4* whr = (const float4*)(w_hh + (size_t)j * H);
    const float4* whz = (const float4*)(w_hh + (size_t)(H + j) * H);
    const float4* whn = (const float4*)(w_hh + (size_t)(2 * H + j) * H);

    float s0 = dot4(wir[t], xv);
    float s1 = dot4(wiz[t], xv);
    float s2 = dot4(win[t], xv);
    float s3 = dot4(whr[t], hv);
    float s4 = dot4(whz[t], hv);
    float s5 = dot4(whn[t], hv);

    __shared__ float red[8][6];
    s0 = warp_sum(s0); s1 = warp_sum(s1); s2 = warp_sum(s2);
    s3 = warp_sum(s3); s4 = warp_sum(s4); s5 = warp_sum(s5);
    const int w = t >> 5, lane = t & 31;
    if (lane == 0) {
        red[w][0] = s0; red[w][1] = s1; red[w][2] = s2;
        red[w][3] = s3; red[w][4] = s4; red[w][5] = s5;
    }
    __syncthreads();
    if (t == 0) {
        float a[6] = {0, 0, 0, 0, 0, 0};
#pragma unroll
        for (int i = 0; i < 8; i++)
#pragma unroll
            for (int k = 0; k < 6; k++) a[k] += red[i][k];
        const float r = 1.f / (1.f + __expf(-(a[0] + b_ih[j] + a[3] + b_hh[j])));
        const float z = 1.f / (1.f + __expf(-(a[1] + b_ih[H + j] + a[4] + b_hh[H + j])));
        const float n = tanhf(a[2] + b_ih[2 * H + j] + r * (a[5] + b_hh[2 * H + j]));
        const float hn = (1.f - z) * n + z * hidden[j];
        g_hnew[j] = hn;
        g_concat[H + j] = hn;
        d_out[V + j] = hn;  // second tuple element of the reference output
    }
}

// ---------------------------------------------------------------------------
// 2) Attention scores: warp per encoder row. grid = L/8, block = 256.
// ---------------------------------------------------------------------------
__global__ void scores_kernel(const float* __restrict__ enc) {
    const int w = threadIdx.x >> 5, lane = threadIdx.x & 31;
    const int l = blockIdx.x * 8 + w;
    const float4* e4 = (const float4*)(enc + (size_t)l * H);
    const float4* h4 = (const float4*)g_hnew;
    float s = 0.f;
#pragma unroll
    for (int i = 0; i < 8; i++) s += dot4(e4[lane + i * 32], h4[lane + i * 32]);
    s = warp_sum(s);
    if (lane == 0) g_scores[l] = s;
}

// ---------------------------------------------------------------------------
// 3) Softmax over L=4096 scores; one 1024-thread block.
// ---------------------------------------------------------------------------
__global__ void softmax_kernel() {
    const int t = threadIdx.x;
    __shared__ float red[32];
    __shared__ float bmax, bsum;

    const float v0 = g_scores[t];
    const float v1 = g_scores[t + 1024];
    const float v2 = g_scores[t + 2048];
    const float v3 = g_scores[t + 3072];

    float m = fmaxf(fmaxf(v0, v1), fmaxf(v2, v3));
    m = warp_max(m);
    if ((t & 31) == 0) red[t >> 5] = m;
    __syncthreads();
    if (t < 32) {
        float x = red[t];
        x = warp_max(x);
        if (t == 0) bmax = x;
    }
    __syncthreads();
    const float mm = bmax;

    const float e0 = __expf(v0 - mm), e1 = __expf(v1 - mm);
    const float e2 = __expf(v2 - mm), e3 = __expf(v3 - mm);
    float s = e0 + e1 + e2 + e3;
    s = warp_sum(s);
    if ((t & 31) == 0) red[t >> 5] = s;
    __syncthreads();
    if (t < 32) {
        float x = red[t];
        x = warp_sum(x);
        if (t == 0) bsum = x;
    }
    __syncthreads();
    const float inv = 1.f / bsum;

    g_attn[t]        = e0 * inv;
    g_attn[t + 1024] = e1 * inv;
    g_attn[t + 2048] = e2 * inv;
    g_attn[t + 3072] = e3 * inv;
}

// ---------------------------------------------------------------------------
// 4a) ctx partials: block b covers rows [32b, 32b+32); thread c owns float4
//     column c. 32 independent unrolled loads per thread, NO atomics.
// ---------------------------------------------------------------------------
__global__ void ctx_part_kernel(const float* __restrict__ enc) {
    const int c = threadIdx.x;        // float4 column 0..255
    const int l0 = blockIdx.x * 32;
    __shared__ float a[32];
    if (c < 32) a[c] = g_attn[l0 + c];
    __syncthreads();

    const float4* e4 = (const float4*)enc;
    float4 acc = make_float4(0.f, 0.f, 0.f, 0.f);
#pragma unroll
    for (int i = 0; i < 32; i++) {
        const float4 e = e4[(size_t)(l0 + i) * 256 + c];
        const float w = a[i];
        acc.x += w * e.x; acc.y += w * e.y;
        acc.z += w * e.z; acc.w += w * e.w;
    }
    ((float4*)g_ctxp[blockIdx.x])[c] = acc;
}

// ---------------------------------------------------------------------------
// 4b) ctx reduce: 32 blocks x 256 threads. Block b owns columns
//     [32b, 32b+32); thread = (chunk = tid/32) x (col = tid%32); each thread
//     sums 16 partials (coalesced), then shared combine over 8 chunks.
// ---------------------------------------------------------------------------
__global__ void ctx_reduce_kernel() {
    const int col = blockIdx.x * 32 + (threadIdx.x & 31);
    const int chunk = threadIdx.x >> 5;          // 0..7
    float s = 0.f;
#pragma unroll
    for (int p = 0; p < 16; p++) s += g_ctxp[chunk * 16 + p][col];
    __shared__ float sh[8][32];
    sh[chunk][threadIdx.x & 31] = s;
    __syncthreads();
    if (chunk == 0) {
        float t = 0.f;
#pragma unroll
        for (int k = 0; k < 8; k++) t += sh[k][threadIdx.x & 31];
        g_concat[col] = t;
    }
}

// ---------------------------------------------------------------------------
// 5) logits = out_w @ concat + out_b. Warp per vocab row; concat staged in
//    shared once per block. The big one (412 MB of weights).
// ---------------------------------------------------------------------------
__global__ void logits_kernel(const float* __restrict__ out_w,
                              const float* __restrict__ out_b) {
    __shared__ float4 csh[512];   // 2H floats
    const int t = threadIdx.x;
    const float4* cg = (const float4*)g_concat;
    csh[t] = cg[t];
    csh[t + 256] = cg[t + 256];
    __syncthreads();

    const int w = t >> 5, lane = t & 31;
    const int v = blockIdx.x * 8 + w;
    if (v >= V) return;
    const float4* w4 = (const float4*)(out_w + (size_t)v * 2 * H);
    float s = 0.f;
#pragma unroll
    for (int i = 0; i < 16; i++) s += dot4(w4[lane + i * 32], csh[lane + i * 32]);
    s = warp_sum(s);
    if (lane == 0) g_logits[v] = s + out_b[v];
}

// ---------------------------------------------------------------------------
// 6) LSE stage 1: 32 blocks × 256 threads -> (max, sumexp) per block.
// ---------------------------------------------------------------------------
__global__ void lse_part_kernel() {
    const int b = blockIdx.x, t = threadIdx.x;
    const int chunk = (V + NPART - 1) / NPART;        // 1571
    const int lo = b * chunk;
    const int hi = min(lo + chunk, V);

    __shared__ float red[8];
    __shared__ float bmax;

    float m = -3.4e38f;
    for (int i = lo + t; i < hi; i += 256) m = fmaxf(m, g_logits[i]);
    m = warp_max(m);
    if ((t & 31) == 0) red[t >> 5] = m;
    __syncthreads();
    if (t < 8) {
        float x = red[t];
#pragma unroll
        for (int o = 4; o; o >>= 1) x = fmaxf(x, __shfl_xor_sync(0xffu, x, o));
        if (t == 0) bmax = x;
    }
    __syncthreads();
    const float mm = bmax;

    float s = 0.f;
    for (int i = lo + t; i < hi; i += 256) s += __expf(g_logits[i] - mm);
    s = warp_sum(s);
    if ((t & 31) == 0) red[t >> 5] = s;
    __syncthreads();
    if (t < 8) {
        float x = red[t];
#pragma unroll
        for (int o = 4; o; o >>= 1) x += __shfl_xor_sync(0xffu, x, o);
        if (t == 0) { g_pmax[b] = mm; g_psum[b] = x; }
    }
}

// ---------------------------------------------------------------------------
// 7) finalize: warp 0 merges the 32 (max,sumexp) partials online, then the
//    whole block writes out[v] = logits[v] - lse.
// ---------------------------------------------------------------------------
__global__ void final_kernel(float* __restrict__ d_out) {
    __shared__ float lse_s;
    const int t = threadIdx.x;
    if (t < 32) {
        float m = g_pmax[t];
        float s = g_psum[t];
#pragma unroll
        for (int o = 16; o; o >>= 1) {
            const float om = __shfl_xor_sync(0xffffffffu, m, o);
            const float os = __shfl_xor_sync(0xffffffffu, s, o);
            const float M = fmaxf(m, om);
            s = s * __expf(m - M) + os * __expf(om - M);
            m = M;
        }
        if (t == 0) lse_s = m + logf(s);
    }
    __syncthreads();
    const float lse = lse_s;
    const int v = blockIdx.x * 256 + t;
    if (v < V) d_out[v] = g_logits[v] - lse;
}

extern "C" void kernel_launch(void* const* d_in, const int* in_sizes, int n_in,
                              void* d_out, int out_size) {
    const int*   input  = (const int*)d_in[0];
    const float* hidden = (const float*)d_in[1];
    const float* enc    = (const float*)d_in[2];
    const float* emb    = (const float*)d_in[3];
    const float* w_ih   = (const float*)d_in[4];
    const float* w_hh   = (const float*)d_in[5];
    const float* b_ih   = (const float*)d_in[6];
    const float* b_hh   = (const float*)d_in[7];
    const float* out_w  = (const float*)d_in[8];
    const float* out_b  = (const float*)d_in[9];
    float* out = (float*)d_out;

    gru_kernel<<<H, 256>>>(input, hidden, emb, w_ih, w_hh, b_ih, b_hh, out);
    scores_kernel<<<L / 8, 256>>>(enc);
    softmax_kernel<<<1, 1024>>>();
    ctx_part_kernel<<<CPART, 256>>>(enc);
    ctx_reduce_kernel<<<32, 256>>>();
    logits_kernel<<<(V + 7) / 8, 256>>>(out_w, out_b);
    lse_part_kernel<<<NPART, 256>>>();
    final_kernel<<<(V + 255) / 256, 256>>>(out);
}